// round 5
// baseline (speedup 1.0000x reference)
#include <cuda_runtime.h>

// SideWindowFilter: 24 planes of 768x768 fp32, r=2, 3 iterations.
// Per pixel: 6 box sums -> 8 directional means -> argmin |mean - x| -> x += d.
// Argmin done predicate-free: key = rotl(bits(d),1) orders by |d| (sign in LSB),
// umin tree, rotr recovers d. All lat-4 ALU ops, no 13-cyc predicate chains.

#define HH 768
#define WW 768
#define NPLANES 24
#define TW 64          // tile width
#define TH 64          // tile height
#define RPT 16         // rows per thread; block = (32,4) = 128 threads
#define XS 68          // tile + 2*2 halo

typedef unsigned long long u64;
typedef unsigned int u32;

__device__ float g_scratch[NPLANES * HH * WW];

__device__ __forceinline__ u64 pk(float lo, float hi) {
    u64 r; asm("mov.b64 %0, {%1, %2};" : "=l"(r) : "f"(lo), "f"(hi)); return r;
}
__device__ __forceinline__ u64 fadd2(u64 a, u64 b) {
    u64 r; asm("add.rn.f32x2 %0, %1, %2;" : "=l"(r) : "l"(a), "l"(b)); return r;
}
__device__ __forceinline__ u64 ffma2(u64 a, u64 b, u64 c) {
    u64 r; asm("fma.rn.f32x2 %0, %1, %2, %3;" : "=l"(r) : "l"(a), "l"(b), "l"(c)); return r;
}
__device__ __forceinline__ float2 asf2(u64 v) {
    union { u64 u; float2 f; } cv; cv.u = v; return cv.f;
}
// |d|-ordered unsigned key with sign in bit0; rotr inverts exactly.
__device__ __forceinline__ u32 keyof(float d) {
    return __funnelshift_l(__float_as_uint(d), __float_as_uint(d), 1);
}
__device__ __forceinline__ float unkey(u32 k) {
    return __uint_as_float(__funnelshift_r(k, k, 1));
}

// Build per-row horizontal sums for a 2-col window: loads 6 floats (3 LDS.64).
//   A = {x0+x1+x2, x1+x2+x3}   B = {x2+x3+x4, x3+x4+x5}
//   F = {x0..x4,   x1..x5}     C = {x2, x3}
#define ROWBUILD(rr, A, B, F, C) do {                                   \
    const float2* f2r = (const float2*)xs[rr];                          \
    const float2 p0 = f2r[tx], p1 = f2r[tx + 1], p2 = f2r[tx + 2];      \
    const float u = p0.y + p1.x;                                        \
    const float v = p1.y + p2.x;                                        \
    const float w = u + v;                                              \
    A = pk(u + p0.x, u + p1.y);                                         \
    B = pk(v + p1.x, v + p2.y);                                         \
    F = pk(w + p0.x, w + p2.y);                                         \
    C = pk(p1.x, p1.y);                                                 \
} while (0)

__global__ __launch_bounds__(128)
void swf_step(const float* __restrict__ in_ext, float* __restrict__ out_ext,
              int in_is_scratch, int out_is_scratch)
{
    __shared__ float xs[XS][XS];   // 18.5 KB

    const float* __restrict__ in  = in_is_scratch  ? (const float*)g_scratch : in_ext;
    float* __restrict__       out = out_is_scratch ? (float*)g_scratch       : out_ext;

    const int plane = blockIdx.z;
    const int gx0 = blockIdx.x * TW;
    const int gy0 = blockIdx.y * TH;
    const float* __restrict__ pin = in  + (size_t)plane * HH * WW;
    float* __restrict__ pout      = out + (size_t)plane * HH * WW;

    const int tx = threadIdx.x;      // 0..31 -> col pair 2*tx
    const int ty = threadIdx.y;      // 0..3  -> row group of 16

    // ---- Phase 1: load 68x68 tile (+halo) ----
    const bool interior = (gx0 >= 2) & (gx0 + XS - 2 <= WW) &
                          (gy0 >= 2) & (gy0 + XS - 2 <= HH);
    if (interior) {
        const float* src0 = pin + (size_t)(gy0 - 2) * WW + (gx0 - 2);
        #pragma unroll
        for (int r = ty; r < XS; r += 4) {
            const float* src = src0 + (size_t)r * WW;
            xs[r][tx]      = __ldg(&src[tx]);
            xs[r][tx + 32] = __ldg(&src[tx + 32]);
            if (tx < XS - TW) xs[r][tx + 64] = __ldg(&src[tx + 64]);
        }
    } else {
        #pragma unroll
        for (int r = ty; r < XS; r += 4) {
            const int gy = gy0 - 2 + r;
            const bool yok = (unsigned)gy < HH;
            const int gxa = gx0 - 2 + tx;
            float v0 = 0.0f, v1 = 0.0f;
            if (yok && (unsigned)gxa < WW)        v0 = __ldg(&pin[(size_t)gy * WW + gxa]);
            xs[r][tx] = v0;
            if (yok && (unsigned)(gxa + 32) < WW) v1 = __ldg(&pin[(size_t)gy * WW + gxa + 32]);
            xs[r][tx + 32] = v1;
            if (tx < XS - TW) {
                float v2 = 0.0f;
                if (yok && (unsigned)(gxa + 64) < WW) v2 = __ldg(&pin[(size_t)gy * WW + gxa + 64]);
                xs[r][tx + 64] = v2;
            }
        }
    }
    __syncthreads();

    const u64 K15 = pk(1.0f / 15.0f, 1.0f / 15.0f);
    const u64 K9  = pk(1.0f / 9.0f,  1.0f / 9.0f);
    const u64 K81 = pk(1.0f / 81.0f, 1.0f / 81.0f);

    const int r0 = ty * RPT;

    // ---- Warm-up: rows r0..r0+4 ----
    u64 A0, A1, A2, A3, A4;
    u64 B0, B1, B2, B3, B4;
    u64 F0, F1, F2, F3, F4;
    u64 Cd, C2, C3, C4;
    ROWBUILD(r0 + 0, A0, B0, F0, Cd);
    ROWBUILD(r0 + 1, A1, B1, F1, Cd);
    ROWBUILD(r0 + 2, A2, B2, F2, C2);
    ROWBUILD(r0 + 3, A3, B3, F3, C3);
    ROWBUILD(r0 + 4, A4, B4, F4, C4);
    (void)Cd;

    float2* pw = (float2*)(pout + (size_t)(gy0 + r0) * WW + (gx0 + 2 * tx));

    #pragma unroll
    for (int s = 0; s < RPT; s++) {
        const u64 S_tl = fadd2(fadd2(A0, A1), A2);
        const u64 S_bl = fadd2(fadd2(A2, A3), A4);
        const u64 S_lf = fadd2(fadd2(S_tl, A3), A4);
        const u64 S_rt = fadd2(fadd2(fadd2(B0, B1), fadd2(B2, B3)), B4);
        const u64 S_tp = fadd2(fadd2(F0, F1), F2);
        const u64 S_bt = fadd2(fadd2(F2, F3), F4);
        const u64 xc  = C2;
        const u64 nxc = xc ^ 0x8000000080000000ULL;   // packed negate (exact)

        const float2 dL  = asf2(ffma2(S_lf, K15, nxc));
        const float2 dR  = asf2(ffma2(S_rt, K15, nxc));
        const float2 dU  = asf2(ffma2(S_tp, K15, nxc));
        const float2 dD  = asf2(ffma2(S_bt, K15, nxc));
        const float2 dNW = asf2(ffma2(S_tl, K9,  nxc));
        const float2 dNE = asf2(ffma2(S_tl, K81, nxc));
        const float2 dSW = asf2(ffma2(S_bl, K9,  nxc));
        const float2 dSE = asf2(ffma2(S_bl, K81, nxc));
        const float2 xcf = asf2(xc);

        // predicate-free argmin: rotate-key + unsigned-min tree + rotate back
        const u32 m0 = umin(umin(umin(keyof(dL.x),  keyof(dR.x)),
                                 umin(keyof(dU.x),  keyof(dD.x))),
                            umin(umin(keyof(dNW.x), keyof(dNE.x)),
                                 umin(keyof(dSW.x), keyof(dSE.x))));
        const u32 m1 = umin(umin(umin(keyof(dL.y),  keyof(dR.y)),
                                 umin(keyof(dU.y),  keyof(dD.y))),
                            umin(umin(keyof(dNW.y), keyof(dNE.y)),
                                 umin(keyof(dSW.y), keyof(dSE.y))));

        *pw = make_float2(xcf.x + unkey(m0), xcf.y + unkey(m1));
        pw = (float2*)((float*)pw + WW);

        if (s < RPT - 1) {
            A0 = A1; A1 = A2; A2 = A3; A3 = A4;
            B0 = B1; B1 = B2; B2 = B3; B3 = B4;
            F0 = F1; F1 = F2; F2 = F3; F3 = F4;
            C2 = C3; C3 = C4;
            ROWBUILD(r0 + 5 + s, A4, B4, F4, C4);
        }
    }
}

extern "C" void kernel_launch(void* const* d_in, const int* in_sizes, int n_in,
                              void* d_out, int out_size)
{
    const float* x = (const float*)d_in[0];
    float* out = (float*)d_out;

    dim3 block(32, 4);
    dim3 grid(WW / TW, HH / TH, NPLANES);

    // iteration = 3 (fixed by setup_inputs)
    swf_step<<<grid, block>>>(x, out, 0, 0);        // x       -> out
    swf_step<<<grid, block>>>(out, nullptr, 0, 1);  // out     -> scratch
    swf_step<<<grid, block>>>(nullptr, out, 1, 0);  // scratch -> out
}

// round 6
// speedup vs baseline: 1.1712x; 1.1712x over previous
#include <cuda_runtime.h>

// SideWindowFilter: 24 planes of 768x768 fp32, r=2, 3 iterations.
// Per pixel: 6 box sums -> 8 directional means -> argmin |mean - x| -> x += d.
//   S_left/15, S_right/15, S_top/15, S_bot/15, S_tl/{9,81}, S_bl/{9,81}
// (NE/SE share NW/SW support due to the reference's normalization bug.)

#define HH 768
#define WW 768
#define NPLANES 24
#define TW 64          // tile width
#define TH 64          // tile height
#define RPT 16         // rows per thread; block = (32,4) = 128 threads
#define XS 68          // tile + 2*2 halo

typedef unsigned long long u64;

__device__ float g_scratch[NPLANES * HH * WW];

__device__ __forceinline__ u64 pk(float lo, float hi) {
    u64 r; asm("mov.b64 %0, {%1, %2};" : "=l"(r) : "f"(lo), "f"(hi)); return r;
}
__device__ __forceinline__ u64 fadd2(u64 a, u64 b) {
    u64 r; asm("add.rn.f32x2 %0, %1, %2;" : "=l"(r) : "l"(a), "l"(b)); return r;
}
__device__ __forceinline__ u64 ffma2(u64 a, u64 b, u64 c) {
    u64 r; asm("fma.rn.f32x2 %0, %1, %2, %3;" : "=l"(r) : "l"(a), "l"(b), "l"(c)); return r;
}
__device__ __forceinline__ float2 asf2(u64 v) {
    union { u64 u; float2 f; } cv; cv.u = v; return cv.f;
}
__device__ __forceinline__ u64 asu64(float2 f) {
    union { float2 f; u64 u; } cv; cv.f = f; return cv.u;
}

// Build per-row horizontal sums for a 2-col window: 3 LDS.64 + 5 packed adds.
//   A = {x0+x1+x2, x1+x2+x3}   B = {x2+x3+x4, x3+x4+x5}
//   F = {x0..x4,   x1..x5}     C = {x2, x3}
#define ROWBUILD(rr, A, B, F, C) do {                                   \
    const float2* f2r = (const float2*)xs[rr];                          \
    const float2 p0 = f2r[tx], p1 = f2r[tx + 1], p2 = f2r[tx + 2];      \
    const u64 P0 = asu64(p0), P1 = asu64(p1), P2 = asu64(p2);           \
    const u64 s01 = pk(p0.y, p1.x);                                     \
    const u64 s23 = pk(p1.y, p2.x);                                     \
    const u64 t   = fadd2(s23, P2);                                     \
    A = fadd2(fadd2(P0, s01), P1);                                      \
    B = fadd2(P1, t);                                                   \
    F = fadd2(A, t);                                                    \
    C = P1;                                                             \
} while (0)

__global__ __launch_bounds__(128)
void swf_step(const float* __restrict__ in_ext, float* __restrict__ out_ext,
              int in_is_scratch, int out_is_scratch)
{
    __shared__ float xs[XS][XS];   // 18.5 KB

    const float* __restrict__ in  = in_is_scratch  ? (const float*)g_scratch : in_ext;
    float* __restrict__       out = out_is_scratch ? (float*)g_scratch       : out_ext;

    const int plane = blockIdx.z;
    const int gx0 = blockIdx.x * TW;
    const int gy0 = blockIdx.y * TH;
    const float* __restrict__ pin = in  + (size_t)plane * HH * WW;
    float* __restrict__ pout      = out + (size_t)plane * HH * WW;

    const int tx = threadIdx.x;      // 0..31 -> col pair 2*tx
    const int ty = threadIdx.y;      // 0..3  -> row group of 16

    // ---- Phase 1: load 68x68 tile (+halo) ----
    const bool interior = (gx0 >= 2) & (gx0 + XS - 2 <= WW) &
                          (gy0 >= 2) & (gy0 + XS - 2 <= HH);
    if (interior) {
        const float* src0 = pin + (size_t)(gy0 - 2) * WW + (gx0 - 2);
        #pragma unroll
        for (int r = ty; r < XS; r += 4) {
            const float* src = src0 + (size_t)r * WW;
            xs[r][tx]      = __ldg(&src[tx]);
            xs[r][tx + 32] = __ldg(&src[tx + 32]);
            if (tx < XS - TW) xs[r][tx + 64] = __ldg(&src[tx + 64]);
        }
    } else {
        #pragma unroll
        for (int r = ty; r < XS; r += 4) {
            const int gy = gy0 - 2 + r;
            const bool yok = (unsigned)gy < HH;
            const int gxa = gx0 - 2 + tx;
            float v0 = 0.0f, v1 = 0.0f;
            if (yok && (unsigned)gxa < WW)        v0 = __ldg(&pin[(size_t)gy * WW + gxa]);
            xs[r][tx] = v0;
            if (yok && (unsigned)(gxa + 32) < WW) v1 = __ldg(&pin[(size_t)gy * WW + gxa + 32]);
            xs[r][tx + 32] = v1;
            if (tx < XS - TW) {
                float v2 = 0.0f;
                if (yok && (unsigned)(gxa + 64) < WW) v2 = __ldg(&pin[(size_t)gy * WW + gxa + 64]);
                xs[r][tx + 64] = v2;
            }
        }
    }
    __syncthreads();

    const u64 K15 = pk(1.0f / 15.0f, 1.0f / 15.0f);
    const u64 K9  = pk(1.0f / 9.0f,  1.0f / 9.0f);
    const u64 K81 = pk(1.0f / 81.0f, 1.0f / 81.0f);

    const int r0 = ty * RPT;

    // ---- Warm-up: rows r0..r0+4 ----
    u64 A0, A1, A2, A3, A4;
    u64 B0, B1, B2, B3, B4;
    u64 F0, F1, F2, F3, F4;
    u64 Cd, C2, C3, C4;
    ROWBUILD(r0 + 0, A0, B0, F0, Cd);
    ROWBUILD(r0 + 1, A1, B1, F1, Cd);
    ROWBUILD(r0 + 2, A2, B2, F2, C2);
    ROWBUILD(r0 + 3, A3, B3, F3, C3);
    ROWBUILD(r0 + 4, A4, B4, F4, C4);
    (void)Cd;

    float2* pw = (float2*)(pout + (size_t)(gy0 + r0) * WW + (gx0 + 2 * tx));

    #pragma unroll
    for (int s = 0; s < RPT; s++) {
        const u64 S_tl = fadd2(fadd2(A0, A1), A2);
        const u64 S_bl = fadd2(fadd2(A2, A3), A4);
        const u64 S_lf = fadd2(fadd2(S_tl, A3), A4);
        const u64 S_rt = fadd2(fadd2(fadd2(B0, B1), fadd2(B2, B3)), B4);
        const u64 S_tp = fadd2(fadd2(F0, F1), F2);
        const u64 S_bt = fadd2(fadd2(F2, F3), F4);
        const u64 xc  = C2;
        const u64 nxc = xc ^ 0x8000000080000000ULL;   // packed negate (exact)

        // channel order: L,R,U,D,NW,NE,SW,SE
        const float2 dL  = asf2(ffma2(S_lf, K15, nxc));
        const float2 dR  = asf2(ffma2(S_rt, K15, nxc));
        const float2 dU  = asf2(ffma2(S_tp, K15, nxc));
        const float2 dD  = asf2(ffma2(S_bt, K15, nxc));
        const float2 dNW = asf2(ffma2(S_tl, K9,  nxc));
        const float2 dNE = asf2(ffma2(S_tl, K81, nxc));
        const float2 dSW = asf2(ffma2(S_bl, K9,  nxc));
        const float2 dSE = asf2(ffma2(S_bl, K81, nxc));
        const float2 xcf = asf2(xc);

        // tournament argmin on |d| (FSETP|abs| + FSEL, pred-as-data lat 4);
        // strict '<' keeps lower channel index on ties
        const float a01 = (fabsf(dR.x)  < fabsf(dL.x))  ? dR.x  : dL.x;
        const float a23 = (fabsf(dD.x)  < fabsf(dU.x))  ? dD.x  : dU.x;
        const float a45 = (fabsf(dNE.x) < fabsf(dNW.x)) ? dNE.x : dNW.x;
        const float a67 = (fabsf(dSE.x) < fabsf(dSW.x)) ? dSE.x : dSW.x;
        const float a03 = (fabsf(a23)   < fabsf(a01))   ? a23   : a01;
        const float a47 = (fabsf(a67)   < fabsf(a45))   ? a67   : a45;
        const float best0 = (fabsf(a47) < fabsf(a03))   ? a47   : a03;

        const float b01 = (fabsf(dR.y)  < fabsf(dL.y))  ? dR.y  : dL.y;
        const float b23 = (fabsf(dD.y)  < fabsf(dU.y))  ? dD.y  : dU.y;
        const float b45 = (fabsf(dNE.y) < fabsf(dNW.y)) ? dNE.y : dNW.y;
        const float b67 = (fabsf(dSE.y) < fabsf(dSW.y)) ? dSE.y : dSW.y;
        const float b03 = (fabsf(b23)   < fabsf(b01))   ? b23   : b01;
        const float b47 = (fabsf(b67)   < fabsf(b45))   ? b67   : b45;
        const float best1 = (fabsf(b47) < fabsf(b03))   ? b47   : b03;

        *pw = make_float2(xcf.x + best0, xcf.y + best1);
        pw = (float2*)((float*)pw + WW);

        if (s < RPT - 1) {
            A0 = A1; A1 = A2; A2 = A3; A3 = A4;
            B0 = B1; B1 = B2; B2 = B3; B3 = B4;
            F0 = F1; F1 = F2; F2 = F3; F3 = F4;
            C2 = C3; C3 = C4;
            ROWBUILD(r0 + 5 + s, A4, B4, F4, C4);
        }
    }
}

extern "C" void kernel_launch(void* const* d_in, const int* in_sizes, int n_in,
                              void* d_out, int out_size)
{
    const float* x = (const float*)d_in[0];
    float* out = (float*)d_out;

    dim3 block(32, 4);
    dim3 grid(WW / TW, HH / TH, NPLANES);

    // iteration = 3 (fixed by setup_inputs)
    swf_step<<<grid, block>>>(x, out, 0, 0);        // x       -> out
    swf_step<<<grid, block>>>(out, nullptr, 0, 1);  // out     -> scratch
    swf_step<<<grid, block>>>(nullptr, out, 1, 0);  // scratch -> out
}